// round 16
// baseline (speedup 1.0000x reference)
#include <cuda_runtime.h>
#include <cuda_fp16.h>
#include <cstdint>
#include <math.h>

// ---------------- problem constants ----------------
#define B_  16384
#define N_  10
#define T_  (B_*N_)        // 163840 tokens
#define D_  512

typedef unsigned long long u64;

// ---------------- scratch (static device globals; no allocation) ----------------
__device__ __align__(128) float g_rel[T_*20];
__device__ __align__(128) float g_y  [T_*D_];      // pre-LN sums (fp32, accuracy-critical)
__device__ __align__(128) float g_wc [1536*20];    // composed qkv weight (fp32)
__device__ __align__(128) float g_bc [1536];       // composed qkv bias

__device__ __align__(128) __half g_x16  [T_*D_];   // residual 1 (fp16)
__device__ __align__(128) __half g_qkv16[T_*3*D_];
__device__ __align__(128) __half g_o16  [T_*D_];
__device__ __align__(128) __half g_x116 [T_*D_];   // residual 2 (fp16)
__device__ __align__(128) __half g_h16  [T_*D_];

__device__ __align__(128) __half g_wo16[D_*D_];
__device__ __align__(128) __half g_w116[D_*D_];
__device__ __align__(128) __half g_w216[D_*D_];

// ---------------- small helpers ----------------
__device__ __forceinline__ float warp_sum(float v) {
#pragma unroll
    for (int o = 16; o; o >>= 1) v += __shfl_xor_sync(0xffffffffu, v, o);
    return v;
}
__device__ __forceinline__ float gelu_f(float x) {
    return 0.5f * x * (1.0f + erff(x * 0.70710678118654752440f));
}
__device__ __forceinline__ uint32_t sm_u32(const void* p) {
    uint32_t a;
    asm("{ .reg .u64 t; cvta.to.shared.u64 t, %1; cvt.u32.u64 %0, t; }" : "=r"(a) : "l"(p));
    return a;
}

// ---------------- mma.sync / ldmatrix wrappers ----------------
__device__ __forceinline__ void ldm_x4(uint32_t* r, uint32_t addr) {
    asm volatile("ldmatrix.sync.aligned.m8n8.x4.shared.b16 {%0,%1,%2,%3}, [%4];"
        : "=r"(r[0]), "=r"(r[1]), "=r"(r[2]), "=r"(r[3]) : "r"(addr));
}
__device__ __forceinline__ void mma_f16(float* d, const uint32_t* a, const uint32_t* b) {
    asm volatile("mma.sync.aligned.m16n8k16.row.col.f32.f16.f16.f32 "
        "{%0,%1,%2,%3}, {%4,%5,%6,%7}, {%8,%9}, {%0,%1,%2,%3};"
        : "+f"(d[0]), "+f"(d[1]), "+f"(d[2]), "+f"(d[3])
        : "r"(a[0]), "r"(a[1]), "r"(a[2]), "r"(a[3]), "r"(b[0]), "r"(b[1]));
}
__device__ __forceinline__ void cpa16(uint32_t dst, const void* src) {
    asm volatile("cp.async.cg.shared.global [%0], [%1], 16;" :: "r"(dst), "l"(src) : "memory");
}
#define CP_COMMIT() asm volatile("cp.async.commit_group;" ::: "memory")
#define CP_WAIT2()  asm volatile("cp.async.wait_group 2;" ::: "memory")

// ---------------- fp16 single-pass tensor-core GEMM (R10/R13 config, proven) ----------------
#define TILE_B 10240u
#define BUF_B  (2u*TILE_B)
#define SMEM_G (4u*BUF_B)          // 81920, 4 stages

// EPI: 1 = +bias +res16 -> fp32 C ; 2 = +bias,gelu -> fp16 C16
template<int EPI, int NOUT>
__global__ __launch_bounds__(512, 2)
void mma_gemm(const __half* __restrict__ A16, const __half* __restrict__ W16,
              const float* __restrict__ bias, const __half* __restrict__ res16,
              float* __restrict__ C, __half* __restrict__ C16)
{
    extern __shared__ char smraw[];
    const uint32_t sb = sm_u32(smraw);

    const int tid  = threadIdx.x;
    const int lane = tid & 31;
    const int wid  = tid >> 5;
    const int wm   = wid >> 2;
    const int wn   = wid & 3;
    const int bm   = blockIdx.y * 128;
    const int bn   = blockIdx.x * 128;

    const int lrow = tid >> 2;
    const int lq   = tid & 3;
    const uint32_t sdst = (uint32_t)(lrow * 80 + lq * 16);
    const __half* apA = A16 + (size_t)(bm + lrow) * 512 + lq * 8;
    const __half* wpW = W16 + (size_t)(bn + lrow) * 512 + lq * 8;

    float acc[2][4][4];
#pragma unroll
    for (int mi = 0; mi < 2; mi++)
#pragma unroll
        for (int ni = 0; ni < 4; ni++)
#pragma unroll
            for (int r = 0; r < 4; r++) acc[mi][ni][r] = 0.f;

#pragma unroll
    for (int s = 0; s < 3; s++) {
        const uint32_t base = sb + (uint32_t)s * BUF_B;
        cpa16(base + sdst,          apA + s * 32);
        cpa16(base + TILE_B + sdst, wpW + s * 32);
        CP_COMMIT();
    }

    const uint32_t a_off = (uint32_t)((wm * 32 + (lane & 15)) * 80 + ((lane >> 4) << 4));
    const uint32_t b_off = (uint32_t)((wn * 32 + ((lane >> 4) << 3) + (lane & 7)) * 80
                                      + (((lane >> 3) & 1) << 4));

    uint32_t cur_s = 0;
#pragma unroll 1
    for (int kt = 0; kt < 16; kt++) {
        CP_WAIT2();
        __syncthreads();
        {
            uint32_t nxt_s = cur_s + 3; if (nxt_s >= 4) nxt_s -= 4;
            const uint32_t nxt = sb + nxt_s * BUF_B;
            if (kt + 3 < 16) {
                const int ko = (kt + 3) * 32;
                cpa16(nxt + sdst,          apA + ko);
                cpa16(nxt + TILE_B + sdst, wpW + ko);
            }
            CP_COMMIT();
        }

        const uint32_t cur = sb + cur_s * BUF_B;
        const uint32_t As = cur, Bs = cur + TILE_B;
#pragma unroll
        for (int kk = 0; kk < 2; kk++) {
            const uint32_t kb = kk * 32;
            uint32_t af[2][4], bf[2][4];
            ldm_x4(af[0], As + a_off + kb);
            ldm_x4(af[1], As + a_off + 16*80 + kb);
            ldm_x4(bf[0], Bs + b_off + kb);
            ldm_x4(bf[1], Bs + b_off + 16*80 + kb);
#pragma unroll
            for (int mi = 0; mi < 2; mi++)
#pragma unroll
                for (int ni = 0; ni < 4; ni++)
                    mma_f16(acc[mi][ni], af[mi], &bf[ni >> 1][(ni & 1) * 2]);
        }

        cur_s = (cur_s == 3) ? 0u : cur_s + 1u;
    }

    const int r0 = bm + wm * 32 + (lane >> 2);
    const int c0 = bn + wn * 32 + (lane & 3) * 2;
#pragma unroll
    for (int mi = 0; mi < 2; mi++) {
#pragma unroll
        for (int ni = 0; ni < 4; ni++) {
            const int col = c0 + ni * 8;
            float2 bv = *(const float2*)&bias[col];
#pragma unroll
            for (int h = 0; h < 2; h++) {
                const int row = r0 + mi * 16 + h * 8;
                float v0 = acc[mi][ni][h * 2 + 0] + bv.x;
                float v1 = acc[mi][ni][h * 2 + 1] + bv.y;
                if (EPI == 1) {
                    __half2 rr = *(const __half2*)&res16[(size_t)row * 512 + col];
                    float2 rf = __half22float2(rr);
                    v0 += rf.x; v1 += rf.y;
                    *(float2*)&C[(size_t)row * NOUT + col] = make_float2(v0, v1);
                } else {
                    if (EPI == 2) { v0 = gelu_f(v0); v1 = gelu_f(v1); }
                    __half2 hp; hp.x = __float2half_rn(v0); hp.y = __float2half_rn(v1);
                    *(__half2*)&C16[(size_t)row * NOUT + col] = hp;
                }
            }
        }
    }
}

// ---------------- weight converter (fp32 -> fp16) ----------------
__global__ void cvtw_kernel(const float* __restrict__ src, __half* __restrict__ dst, int n4) {
    int i = blockIdx.x * 256 + threadIdx.x;
    if (i >= n4) return;
    float4 v = *(const float4*)(src + i * 4);
    __half2 p0; p0.x = __float2half_rn(v.x); p0.y = __float2half_rn(v.y);
    __half2 p1; p1.x = __float2half_rn(v.z); p1.y = __float2half_rn(v.w);
    *(__half2*)&dst[i*4]   = p0;
    *(__half2*)&dst[i*4+2] = p1;
}

// ---------------- weight composition (warp-per-output) ----------------
// Wc[o,j] = sum_d wqkv[o,d] * w_in[d,j] (j<20) ; bc[o] = sum_d wqkv[o,d]*b_in[d] + bqkv[o]
__global__ void wc_kernel(const float* __restrict__ wqkv, const float* __restrict__ w_in,
                          const float* __restrict__ b_in, const float* __restrict__ bqkv,
                          float* __restrict__ wc, float* __restrict__ bc) {
    int w = blockIdx.x * 8 + (threadIdx.x >> 5);   // output index, 0..1536*21-1
    int lane = threadIdx.x & 31;
    if (w >= 1536 * 21) return;
    int o = w / 21, j = w % 21;
    const float* wr = wqkv + (size_t)o * 512;
    float s = 0.f;
    if (j < 20) {
#pragma unroll
        for (int k = 0; k < 16; k++) {
            int d = lane + k * 32;
            s = fmaf(wr[d], w_in[d * 20 + j], s);
        }
        s = warp_sum(s);
        if (lane == 0) wc[o * 20 + j] = s;
    } else {
#pragma unroll
        for (int k = 0; k < 16; k++) {
            int d = lane + k * 32;
            s = fmaf(wr[d], b_in[d], s);
        }
        s = warp_sum(s);
        if (lane == 0) bc[o] = s + bqkv[o];
    }
}

// ---------------- kernel 1: boxes -> rel features ----------------
__global__ void rel_kernel(const float* __restrict__ boxes, float* __restrict__ rel) {
    int gw   = (blockIdx.x * blockDim.x + threadIdx.x) >> 5;
    int lane = threadIdx.x & 31;
    if (gw >= B_) return;

    float cx = 0.f, cy = 0.f, bw = 0.f, bh = 0.f;
    if (lane < N_) {
        float4 bx = *(const float4*)(boxes + ((size_t)gw * N_ + lane) * 4);
        cx = (bx.x + bx.z) * 0.5f * (1.0f / 512.0f);
        cy = (bx.y + bx.w) * 0.5f * (1.0f / 512.0f);
        bw = fabsf(bx.z - bx.x) * (1.0f / 512.0f);
        bh = fabsf(bx.w - bx.y) * (1.0f / 512.0f);
    }
    float bd[5] = {INFINITY, INFINITY, INFINITY, INFINITY, INFINITY};
    int   bj[5] = {0, 0, 0, 0, 0};
#pragma unroll
    for (int j = 0; j < N_; j++) {
        float cxj = __shfl_sync(0xffffffffu, cx, j);
        float cyj = __shfl_sync(0xffffffffu, cy, j);
        float dx = cx - cxj, dy = cy - cyj;
        float d  = dx * dx + dy * dy;
        if (lane < N_ && j != lane && d < bd[4]) {
            int p = 4;
            while (p > 0 && d < bd[p-1]) { bd[p] = bd[p-1]; bj[p] = bj[p-1]; p--; }
            bd[p] = d; bj[p] = j;
        }
    }
#pragma unroll
    for (int k = 0; k < 5; k++) {
        int j = bj[k];
        float cxj = __shfl_sync(0xffffffffu, cx, j);
        float cyj = __shfl_sync(0xffffffffu, cy, j);
        float bwj = __shfl_sync(0xffffffffu, bw, j);
        float bhj = __shfl_sync(0xffffffffu, bh, j);
        if (lane < N_) {
            float4 o4 = make_float4(cxj - cx, cyj - cy, bwj - bw, bhj - bh);
            *(float4*)(rel + ((size_t)gw * N_ + lane) * 20 + k * 4) = o4;
        }
    }
}

// ---------------- fused projection: x16 (slice 0) + qkv16 (slices 1-3), 8-wide stores ----------------
__global__ void proj_kernel(const float* __restrict__ rel,
                            const float* __restrict__ w_in, const float* __restrict__ b_in,
                            const float* __restrict__ wc,   const float* __restrict__ bc,
                            __half* __restrict__ x16, __half* __restrict__ qkv16) {
    __shared__ float ws[20 * 512];
    __shared__ float bs[512];
    __shared__ float rs[32 * 20];
    const int tid   = threadIdx.x;
    const int t0    = blockIdx.x * 32;
    const int slice = blockIdx.y;

    if (slice == 0) {
        for (int i = tid; i < 20 * 512; i += 256) {
            int d = i / 20, j = i % 20;
            ws[j * 512 + d] = w_in[i];
        }
        for (int i = tid; i < 512; i += 256) bs[i] = b_in[i];
    } else {
        int obase = (slice - 1) * 512;
        for (int i = tid; i < 20 * 512; i += 256) {
            int c = i / 20, j = i % 20;
            ws[j * 512 + c] = wc[(size_t)(obase + c) * 20 + j];
        }
        for (int i = tid; i < 512; i += 256) bs[i] = bc[obase + i];
    }
    for (int i = tid; i < 32 * 20; i += 256)
        rs[i] = rel[(size_t)t0 * 20 + i];
    __syncthreads();

    const int obase = (slice - 1) * 512;
    // 32 rows * 64 groups of 8 channels = 2048 items, 8 per thread
    for (int i = tid; i < 32 * 64; i += 256) {
        int tt = i >> 6;
        int c  = (i & 63) * 8;
        float s[8];
#pragma unroll
        for (int e = 0; e < 8; e++) s[e] = bs[c + e];
#pragma unroll
        for (int j = 0; j < 20; j++) {
            float r = rs[tt * 20 + j];
            const float* wj = &ws[j * 512 + c];
#pragma unroll
            for (int e = 0; e < 8; e++) s[e] = fmaf(r, wj[e], s[e]);
        }
        uint4 pack;
        __half2* hp = (__half2*)&pack;
#pragma unroll
        for (int e = 0; e < 4; e++) {
            hp[e].x = __float2half_rn(s[2*e]);
            hp[e].y = __float2half_rn(s[2*e+1]);
        }
        int t = t0 + tt;
        if (slice == 0)
            *(uint4*)&x16[(size_t)t * 512 + c] = pack;
        else
            *(uint4*)&qkv16[(size_t)t * 1536 + obase + c] = pack;
    }
}

// ---------------- attention kernel (fp16 in, fp16 out, 256 threads — proven) ----------------
#define QKVP 1544
__global__ void attn_kernel(const __half* __restrict__ qkv, __half* __restrict__ o) {
    extern __shared__ __align__(16) __half s16[];
    __shared__ float satt[200];
    const int b   = blockIdx.x;
    const int tid = threadIdx.x;
    const __half* src = qkv + (size_t)b * (N_ * 3 * D_);

    for (int i = tid; i < (N_ * 3 * D_) / 8; i += 256) {
        int e = i * 8;
        int r = e / 1536, c = e % 1536;
        *(uint4*)(s16 + r * QKVP + c) = *(const uint4*)(src + e);
    }
    __syncthreads();

    if (tid < 200) {
        int h = tid / 100;
        int i = (tid / 10) % 10;
        int j = tid % 10;
        const __half2* qp = (const __half2*)(s16 + i * QKVP + h * 256);
        const __half2* kp = (const __half2*)(s16 + j * QKVP + 512 + h * 256);
        float acc = 0.f;
#pragma unroll 8
        for (int d = 0; d < 128; d++) {
            float2 qf = __half22float2(qp[d]);
            float2 kf = __half22float2(kp[d]);
            acc = fmaf(qf.x, kf.x, acc);
            acc = fmaf(qf.y, kf.y, acc);
        }
        satt[tid] = acc * 0.0625f;
    }
    __syncthreads();

    if (tid < 20) {
        int base = tid * 10;
        float m = satt[base];
#pragma unroll
        for (int j = 1; j < 10; j++) m = fmaxf(m, satt[base + j]);
        float e[10]; float sum = 0.f;
#pragma unroll
        for (int j = 0; j < 10; j++) { e[j] = expf(satt[base + j] - m); sum += e[j]; }
        float inv = 1.0f / sum;
#pragma unroll
        for (int j = 0; j < 10; j++) satt[base + j] = e[j] * inv;
    }
    __syncthreads();

    __half* dst = o + (size_t)b * (N_ * D_);
    for (int idx = tid; idx < N_ * D_; idx += 256) {
        int d  = idx & 255;
        int hi = idx >> 8;
        int i  = hi % 10, h = hi / 10;
        const float* ap = satt + h * 100 + i * 10;
        const __half* vp = s16 + 1024 + h * 256 + d;
        float acc = 0.f;
#pragma unroll
        for (int j = 0; j < 10; j++) acc = fmaf(ap[j], __half2float(vp[j * QKVP]), acc);
        dst[i * 512 + h * 256 + d] = __float2half_rn(acc);
    }
}

// ---------------- layernorm (fp32 in -> fp16 out) ----------------
__global__ void ln_kernel(const float* __restrict__ y, const float* __restrict__ g,
                          const float* __restrict__ bt, __half* __restrict__ out16) {
    int row  = blockIdx.x * 8 + (threadIdx.x >> 5);
    int lane = threadIdx.x & 31;
    const float* p = y + (size_t)row * 512;
    float v[16];
#pragma unroll
    for (int q = 0; q < 4; q++) {
        float4 t = *(const float4*)(p + q * 128 + lane * 4);
        v[q*4+0] = t.x; v[q*4+1] = t.y; v[q*4+2] = t.z; v[q*4+3] = t.w;
    }
    float s = 0.f;
#pragma unroll
    for (int k = 0; k < 16; k++) s += v[k];
    s = warp_sum(s);
    float mu = s * (1.0f / 512.0f);
    float qs = 0.f;
#pragma unroll
    for (int k = 0; k < 16; k++) { float d = v[k] - mu; qs += d * d; }
    qs = warp_sum(qs);
    float inv = rsqrtf(qs * (1.0f / 512.0f) + 1e-5f);

#pragma unroll
    for (int q = 0; q < 4; q++) {
        int d0 = q * 128 + lane * 4;
        float r[4];
#pragma unroll
        for (int e = 0; e < 4; e++)
            r[e] = (v[q*4+e] - mu) * inv * g[d0+e] + bt[d0+e];
        __half2 hp0; hp0.x = __float2half_rn(r[0]); hp0.y = __float2half_rn(r[1]);
        __half2 hp1; hp1.x = __float2half_rn(r[2]); hp1.y = __float2half_rn(r[3]);
        *(__half2*)&out16[(size_t)row*512 + d0]   = hp0;
        *(__half2*)&out16[(size_t)row*512 + d0+2] = hp1;
    }
}

// ---------------- fused LN2 + LNf (fp32 in -> fp32 out) ----------------
__global__ void ln2f_kernel(const float* __restrict__ y,
                            const float* __restrict__ g2, const float* __restrict__ b2,
                            const float* __restrict__ gf, const float* __restrict__ bf_,
                            float* __restrict__ out) {
    int row  = blockIdx.x * 8 + (threadIdx.x >> 5);
    int lane = threadIdx.x & 31;
    const float* p = y + (size_t)row * 512;
    float v[16];
#pragma unroll
    for (int q = 0; q < 4; q++) {
        float4 t = *(const float4*)(p + q * 128 + lane * 4);
        v[q*4+0] = t.x; v[q*4+1] = t.y; v[q*4+2] = t.z; v[q*4+3] = t.w;
    }
    float s = 0.f;
#pragma unroll
    for (int k = 0; k < 16; k++) s += v[k];
    s = warp_sum(s);
    float mu = s * (1.0f / 512.0f);
    float qs = 0.f;
#pragma unroll
    for (int k = 0; k < 16; k++) { float d = v[k] - mu; qs += d * d; }
    qs = warp_sum(qs);
    float inv = rsqrtf(qs * (1.0f / 512.0f) + 1e-5f);
#pragma unroll
    for (int k = 0; k < 16; k++) {
        int d = (k >> 2) * 128 + lane * 4 + (k & 3);
        v[k] = (v[k] - mu) * inv * g2[d] + b2[d];
    }
    s = 0.f;
#pragma unroll
    for (int k = 0; k < 16; k++) s += v[k];
    s = warp_sum(s);
    float mu2 = s * (1.0f / 512.0f);
    qs = 0.f;
#pragma unroll
    for (int k = 0; k < 16; k++) { float d = v[k] - mu2; qs += d * d; }
    qs = warp_sum(qs);
    float inv2 = rsqrtf(qs * (1.0f / 512.0f) + 1e-5f);

    float* op = out + (size_t)row * 512;
#pragma unroll
    for (int q = 0; q < 4; q++) {
        int d0 = q * 128 + lane * 4;
        float4 r;
        r.x = (v[q*4+0] - mu2) * inv2 * gf[d0+0] + bf_[d0+0];
        r.y = (v[q*4+1] - mu2) * inv2 * gf[d0+1] + bf_[d0+1];
        r.z = (v[q*4+2] - mu2) * inv2 * gf[d0+2] + bf_[d0+2];
        r.w = (v[q*4+3] - mu2) * inv2 * gf[d0+3] + bf_[d0+3];
        *(float4*)(op + d0) = r;
    }
}

// ---------------- launcher ----------------
extern "C" void kernel_launch(void* const* d_in, const int* in_sizes, int n_in,
                              void* d_out, int out_size) {
    const float* boxes = (const float*)d_in[0];
    const float* w_in  = (const float*)d_in[1];
    const float* b_in  = (const float*)d_in[2];
    const float* wqkv  = (const float*)d_in[3];
    const float* bqkv  = (const float*)d_in[4];
    const float* wo    = (const float*)d_in[5];
    const float* bo    = (const float*)d_in[6];
    const float* ln1w  = (const float*)d_in[7];
    const float* ln1b  = (const float*)d_in[8];
    const float* w1    = (const float*)d_in[9];
    const float* b1    = (const float*)d_in[10];
    const float* w2    = (const float*)d_in[11];
    const float* b2    = (const float*)d_in[12];
    const float* ln2w  = (const float*)d_in[13];
    const float* ln2b  = (const float*)d_in[14];
    const float* lnfw  = (const float*)d_in[15];
    const float* lnfb  = (const float*)d_in[16];
    float* out = (float*)d_out;

    float *rel, *yb, *wc, *bc;
    __half *x16, *qkv16, *o16, *x116, *h16;
    __half *wo16, *w116, *w216;
    cudaGetSymbolAddress((void**)&rel,   g_rel);
    cudaGetSymbolAddress((void**)&yb,    g_y);
    cudaGetSymbolAddress((void**)&wc,    g_wc);
    cudaGetSymbolAddress((void**)&bc,    g_bc);
    cudaGetSymbolAddress((void**)&x16,   g_x16);
    cudaGetSymbolAddress((void**)&qkv16, g_qkv16);
    cudaGetSymbolAddress((void**)&o16,   g_o16);
    cudaGetSymbolAddress((void**)&x116,  g_x116);
    cudaGetSymbolAddress((void**)&h16,   g_h16);
    cudaGetSymbolAddress((void**)&wo16,  g_wo16);
    cudaGetSymbolAddress((void**)&w116,  g_w116);
    cudaGetSymbolAddress((void**)&w216,  g_w216);

    cudaFuncSetAttribute(mma_gemm<1,512>, cudaFuncAttributeMaxDynamicSharedMemorySize, SMEM_G);
    cudaFuncSetAttribute(mma_gemm<2,512>, cudaFuncAttributeMaxDynamicSharedMemorySize, SMEM_G);

    // 0) convert weights to fp16 + compose qkv weights (warp-per-output)
    cvtw_kernel<<<(D_*D_/4 + 255)/256, 256>>>(wo, wo16, D_*D_/4);
    cvtw_kernel<<<(D_*D_/4 + 255)/256, 256>>>(w1, w116, D_*D_/4);
    cvtw_kernel<<<(D_*D_/4 + 255)/256, 256>>>(w2, w216, D_*D_/4);
    wc_kernel<<<(1536*21 + 7)/8, 256>>>(wqkv, w_in, b_in, bqkv, wc, bc);
    // 1) relationships
    rel_kernel<<<B_/4, 128>>>(boxes, rel);
    // 2) fused projection: x16 + qkv16 directly from rel (composed weights)
    proj_kernel<<<dim3(T_/32, 4), 256>>>(rel, w_in, b_in, wc, bc, x16, qkv16);
    // 4) attention -> fp16
    int attn_smem = 10 * QKVP * (int)sizeof(__half);
    cudaFuncSetAttribute(attn_kernel, cudaFuncAttributeMaxDynamicSharedMemorySize, attn_smem);
    attn_kernel<<<B_, 256, attn_smem>>>(qkv16, o16);
    // 5) y1 = x16 + o @ wo^T + bo  -> fp32
    mma_gemm<1,512><<<dim3(4, T_/128), 512, SMEM_G>>>(o16, wo16, bo, x16, yb, nullptr);
    // 6) x1 = LN1(y1) -> fp16
    ln_kernel<<<T_/8, 256>>>(yb, ln1w, ln1b, x116);
    // 7) h = gelu(x1 @ w1^T + b1)  -> fp16
    mma_gemm<2,512><<<dim3(4, T_/128), 512, SMEM_G>>>(x116, w116, b1, nullptr, nullptr, h16);
    // 8) y2 = x116 + h @ w2^T + b2  -> fp32
    mma_gemm<1,512><<<dim3(4, T_/128), 512, SMEM_G>>>(h16, w216, b2, x116, yb, nullptr);
    // 9) out = LNf(LN2(y2))
    ln2f_kernel<<<T_/8, 256>>>(yb, ln2w, ln2b, lnfw, lnfb, out);
}

// round 17
// speedup vs baseline: 1.1318x; 1.1318x over previous
#include <cuda_runtime.h>
#include <cuda_fp16.h>
#include <cstdint>
#include <math.h>

// ---------------- problem constants ----------------
#define B_  16384
#define N_  10
#define T_  (B_*N_)        // 163840 tokens
#define D_  512

typedef unsigned long long u64;

// ---------------- scratch (static device globals; no allocation) ----------------
__device__ __align__(128) float g_rel[T_*20];
__device__ __align__(128) float g_y  [T_*D_];      // pre-LN sums (fp32, accuracy-critical)
__device__ __align__(128) float g_wc [1536*20];    // composed qkv weight (fp32)
__device__ __align__(128) float g_bc [1536];       // composed qkv bias

__device__ __align__(128) __half g_x16  [T_*D_];   // residual 1 (fp16)
__device__ __align__(128) __half g_qkv16[T_*3*D_];
__device__ __align__(128) __half g_o16  [T_*D_];
__device__ __align__(128) __half g_x116 [T_*D_];   // residual 2 (fp16)
__device__ __align__(128) __half g_h16  [T_*D_];

__device__ __align__(128) __half g_wo16[D_*D_];
__device__ __align__(128) __half g_w116[D_*D_];
__device__ __align__(128) __half g_w216[D_*D_];

// ---------------- small helpers ----------------
__device__ __forceinline__ float warp_sum(float v) {
#pragma unroll
    for (int o = 16; o; o >>= 1) v += __shfl_xor_sync(0xffffffffu, v, o);
    return v;
}
__device__ __forceinline__ float gelu_f(float x) {
    return 0.5f * x * (1.0f + erff(x * 0.70710678118654752440f));
}
__device__ __forceinline__ uint32_t sm_u32(const void* p) {
    uint32_t a;
    asm("{ .reg .u64 t; cvta.to.shared.u64 t, %1; cvt.u32.u64 %0, t; }" : "=r"(a) : "l"(p));
    return a;
}

// ---------------- mma.sync / ldmatrix wrappers ----------------
__device__ __forceinline__ void ldm_x4(uint32_t* r, uint32_t addr) {
    asm volatile("ldmatrix.sync.aligned.m8n8.x4.shared.b16 {%0,%1,%2,%3}, [%4];"
        : "=r"(r[0]), "=r"(r[1]), "=r"(r[2]), "=r"(r[3]) : "r"(addr));
}
__device__ __forceinline__ void mma_f16(float* d, const uint32_t* a, const uint32_t* b) {
    asm volatile("mma.sync.aligned.m16n8k16.row.col.f32.f16.f16.f32 "
        "{%0,%1,%2,%3}, {%4,%5,%6,%7}, {%8,%9}, {%0,%1,%2,%3};"
        : "+f"(d[0]), "+f"(d[1]), "+f"(d[2]), "+f"(d[3])
        : "r"(a[0]), "r"(a[1]), "r"(a[2]), "r"(a[3]), "r"(b[0]), "r"(b[1]));
}
__device__ __forceinline__ void cpa16(uint32_t dst, const void* src) {
    asm volatile("cp.async.cg.shared.global [%0], [%1], 16;" :: "r"(dst), "l"(src) : "memory");
}
#define CP_COMMIT() asm volatile("cp.async.commit_group;" ::: "memory")
#define CP_WAIT2()  asm volatile("cp.async.wait_group 2;" ::: "memory")

// ---------------- fp16 single-pass tensor-core GEMM (R10/R13 config, proven) ----------------
#define TILE_B 10240u
#define BUF_B  (2u*TILE_B)
#define SMEM_G (4u*BUF_B)          // 81920, 4 stages

// EPI: 1 = +bias +res16 -> fp32 C ; 2 = +bias,gelu -> fp16 C16
template<int EPI, int NOUT>
__global__ __launch_bounds__(512, 2)
void mma_gemm(const __half* __restrict__ A16, const __half* __restrict__ W16,
              const float* __restrict__ bias, const __half* __restrict__ res16,
              float* __restrict__ C, __half* __restrict__ C16)
{
    extern __shared__ char smraw[];
    const uint32_t sb = sm_u32(smraw);

    const int tid  = threadIdx.x;
    const int lane = tid & 31;
    const int wid  = tid >> 5;
    const int wm   = wid >> 2;
    const int wn   = wid & 3;
    const int bm   = blockIdx.y * 128;
    const int bn   = blockIdx.x * 128;

    const int lrow = tid >> 2;
    const int lq   = tid & 3;
    const uint32_t sdst = (uint32_t)(lrow * 80 + lq * 16);
    const __half* apA = A16 + (size_t)(bm + lrow) * 512 + lq * 8;
    const __half* wpW = W16 + (size_t)(bn + lrow) * 512 + lq * 8;

    float acc[2][4][4];
#pragma unroll
    for (int mi = 0; mi < 2; mi++)
#pragma unroll
        for (int ni = 0; ni < 4; ni++)
#pragma unroll
            for (int r = 0; r < 4; r++) acc[mi][ni][r] = 0.f;

#pragma unroll
    for (int s = 0; s < 3; s++) {
        const uint32_t base = sb + (uint32_t)s * BUF_B;
        cpa16(base + sdst,          apA + s * 32);
        cpa16(base + TILE_B + sdst, wpW + s * 32);
        CP_COMMIT();
    }

    const uint32_t a_off = (uint32_t)((wm * 32 + (lane & 15)) * 80 + ((lane >> 4) << 4));
    const uint32_t b_off = (uint32_t)((wn * 32 + ((lane >> 4) << 3) + (lane & 7)) * 80
                                      + (((lane >> 3) & 1) << 4));

    uint32_t cur_s = 0;
#pragma unroll 1
    for (int kt = 0; kt < 16; kt++) {
        CP_WAIT2();
        __syncthreads();
        {
            uint32_t nxt_s = cur_s + 3; if (nxt_s >= 4) nxt_s -= 4;
            const uint32_t nxt = sb + nxt_s * BUF_B;
            if (kt + 3 < 16) {
                const int ko = (kt + 3) * 32;
                cpa16(nxt + sdst,          apA + ko);
                cpa16(nxt + TILE_B + sdst, wpW + ko);
            }
            CP_COMMIT();
        }

        const uint32_t cur = sb + cur_s * BUF_B;
        const uint32_t As = cur, Bs = cur + TILE_B;
#pragma unroll
        for (int kk = 0; kk < 2; kk++) {
            const uint32_t kb = kk * 32;
            uint32_t af[2][4], bf[2][4];
            ldm_x4(af[0], As + a_off + kb);
            ldm_x4(af[1], As + a_off + 16*80 + kb);
            ldm_x4(bf[0], Bs + b_off + kb);
            ldm_x4(bf[1], Bs + b_off + 16*80 + kb);
#pragma unroll
            for (int mi = 0; mi < 2; mi++)
#pragma unroll
                for (int ni = 0; ni < 4; ni++)
                    mma_f16(acc[mi][ni], af[mi], &bf[ni >> 1][(ni & 1) * 2]);
        }

        cur_s = (cur_s == 3) ? 0u : cur_s + 1u;
    }

    const int r0 = bm + wm * 32 + (lane >> 2);
    const int c0 = bn + wn * 32 + (lane & 3) * 2;
#pragma unroll
    for (int mi = 0; mi < 2; mi++) {
#pragma unroll
        for (int ni = 0; ni < 4; ni++) {
            const int col = c0 + ni * 8;
            float2 bv = *(const float2*)&bias[col];
#pragma unroll
            for (int h = 0; h < 2; h++) {
                const int row = r0 + mi * 16 + h * 8;
                float v0 = acc[mi][ni][h * 2 + 0] + bv.x;
                float v1 = acc[mi][ni][h * 2 + 1] + bv.y;
                if (EPI == 1) {
                    __half2 rr = *(const __half2*)&res16[(size_t)row * 512 + col];
                    float2 rf = __half22float2(rr);
                    v0 += rf.x; v1 += rf.y;
                    *(float2*)&C[(size_t)row * NOUT + col] = make_float2(v0, v1);
                } else {
                    if (EPI == 2) { v0 = gelu_f(v0); v1 = gelu_f(v1); }
                    __half2 hp; hp.x = __float2half_rn(v0); hp.y = __float2half_rn(v1);
                    *(__half2*)&C16[(size_t)row * NOUT + col] = hp;
                }
            }
        }
    }
}

// ---------------- weight converter (fp32 -> fp16) ----------------
__global__ void cvtw_kernel(const float* __restrict__ src, __half* __restrict__ dst, int n4) {
    int i = blockIdx.x * 256 + threadIdx.x;
    if (i >= n4) return;
    float4 v = *(const float4*)(src + i * 4);
    __half2 p0; p0.x = __float2half_rn(v.x); p0.y = __float2half_rn(v.y);
    __half2 p1; p1.x = __float2half_rn(v.z); p1.y = __float2half_rn(v.w);
    *(__half2*)&dst[i*4]   = p0;
    *(__half2*)&dst[i*4+2] = p1;
}

// ---------------- weight composition (warp-per-output, R16 proven) ----------------
__global__ void wc_kernel(const float* __restrict__ wqkv, const float* __restrict__ w_in,
                          const float* __restrict__ b_in, const float* __restrict__ bqkv,
                          float* __restrict__ wc, float* __restrict__ bc) {
    int w = blockIdx.x * 8 + (threadIdx.x >> 5);   // output index, 0..1536*21-1
    int lane = threadIdx.x & 31;
    if (w >= 1536 * 21) return;
    int o = w / 21, j = w % 21;
    const float* wr = wqkv + (size_t)o * 512;
    float s = 0.f;
    if (j < 20) {
#pragma unroll
        for (int k = 0; k < 16; k++) {
            int d = lane + k * 32;
            s = fmaf(wr[d], w_in[d * 20 + j], s);
        }
        s = warp_sum(s);
        if (lane == 0) wc[o * 20 + j] = s;
    } else {
#pragma unroll
        for (int k = 0; k < 16; k++) {
            int d = lane + k * 32;
            s = fmaf(wr[d], b_in[d], s);
        }
        s = warp_sum(s);
        if (lane == 0) bc[o] = s + bqkv[o];
    }
}

// ---------------- kernel 1: boxes -> rel features ----------------
__global__ void rel_kernel(const float* __restrict__ boxes, float* __restrict__ rel) {
    int gw   = (blockIdx.x * blockDim.x + threadIdx.x) >> 5;
    int lane = threadIdx.x & 31;
    if (gw >= B_) return;

    float cx = 0.f, cy = 0.f, bw = 0.f, bh = 0.f;
    if (lane < N_) {
        float4 bx = *(const float4*)(boxes + ((size_t)gw * N_ + lane) * 4);
        cx = (bx.x + bx.z) * 0.5f * (1.0f / 512.0f);
        cy = (bx.y + bx.w) * 0.5f * (1.0f / 512.0f);
        bw = fabsf(bx.z - bx.x) * (1.0f / 512.0f);
        bh = fabsf(bx.w - bx.y) * (1.0f / 512.0f);
    }
    float bd[5] = {INFINITY, INFINITY, INFINITY, INFINITY, INFINITY};
    int   bj[5] = {0, 0, 0, 0, 0};
#pragma unroll
    for (int j = 0; j < N_; j++) {
        float cxj = __shfl_sync(0xffffffffu, cx, j);
        float cyj = __shfl_sync(0xffffffffu, cy, j);
        float dx = cx - cxj, dy = cy - cyj;
        float d  = dx * dx + dy * dy;
        if (lane < N_ && j != lane && d < bd[4]) {
            int p = 4;
            while (p > 0 && d < bd[p-1]) { bd[p] = bd[p-1]; bj[p] = bj[p-1]; p--; }
            bd[p] = d; bj[p] = j;
        }
    }
#pragma unroll
    for (int k = 0; k < 5; k++) {
        int j = bj[k];
        float cxj = __shfl_sync(0xffffffffu, cx, j);
        float cyj = __shfl_sync(0xffffffffu, cy, j);
        float bwj = __shfl_sync(0xffffffffu, bw, j);
        float bhj = __shfl_sync(0xffffffffu, bh, j);
        if (lane < N_) {
            float4 o4 = make_float4(cxj - cx, cyj - cy, bwj - bw, bhj - bh);
            *(float4*)(rel + ((size_t)gw * N_ + lane) * 20 + k * 4) = o4;
        }
    }
}

// ---------------- fused projection (R15 2-wide version, proven) ----------------
__global__ void proj_kernel(const float* __restrict__ rel,
                            const float* __restrict__ w_in, const float* __restrict__ b_in,
                            const float* __restrict__ wc,   const float* __restrict__ bc,
                            __half* __restrict__ x16, __half* __restrict__ qkv16) {
    __shared__ float ws[20 * 512];
    __shared__ float bs[512];
    __shared__ float rs[32 * 20];
    const int tid   = threadIdx.x;
    const int t0    = blockIdx.x * 32;
    const int slice = blockIdx.y;

    if (slice == 0) {
        for (int i = tid; i < 20 * 512; i += 256) {
            int d = i / 20, j = i % 20;
            ws[j * 512 + d] = w_in[i];
        }
        for (int i = tid; i < 512; i += 256) bs[i] = b_in[i];
    } else {
        int obase = (slice - 1) * 512;
        for (int i = tid; i < 20 * 512; i += 256) {
            int c = i / 20, j = i % 20;
            ws[j * 512 + c] = wc[(size_t)(obase + c) * 20 + j];
        }
        for (int i = tid; i < 512; i += 256) bs[i] = bc[obase + i];
    }
    for (int i = tid; i < 32 * 20; i += 256)
        rs[i] = rel[(size_t)t0 * 20 + i];
    __syncthreads();

    const int obase = (slice - 1) * 512;
    for (int i = tid; i < 32 * 256; i += 256) {
        int tt = i >> 8;
        int c  = (i & 255) * 2;
        float s0 = bs[c], s1 = bs[c + 1];
#pragma unroll
        for (int j = 0; j < 20; j++) {
            float r = rs[tt * 20 + j];
            s0 = fmaf(r, ws[j * 512 + c],     s0);
            s1 = fmaf(r, ws[j * 512 + c + 1], s1);
        }
        int t = t0 + tt;
        __half2 hp; hp.x = __float2half_rn(s0); hp.y = __float2half_rn(s1);
        if (slice == 0)
            *(__half2*)&x16[(size_t)t * 512 + c] = hp;
        else
            *(__half2*)&qkv16[(size_t)t * 1536 + obase + c] = hp;
    }
}

// ---------------- attention kernel (fp16 in, fp16 out, 256 threads — proven) ----------------
#define QKVP 1544
__global__ void attn_kernel(const __half* __restrict__ qkv, __half* __restrict__ o) {
    extern __shared__ __align__(16) __half s16[];
    __shared__ float satt[200];
    const int b   = blockIdx.x;
    const int tid = threadIdx.x;
    const __half* src = qkv + (size_t)b * (N_ * 3 * D_);

    for (int i = tid; i < (N_ * 3 * D_) / 8; i += 256) {
        int e = i * 8;
        int r = e / 1536, c = e % 1536;
        *(uint4*)(s16 + r * QKVP + c) = *(const uint4*)(src + e);
    }
    __syncthreads();

    if (tid < 200) {
        int h = tid / 100;
        int i = (tid / 10) % 10;
        int j = tid % 10;
        const __half2* qp = (const __half2*)(s16 + i * QKVP + h * 256);
        const __half2* kp = (const __half2*)(s16 + j * QKVP + 512 + h * 256);
        float acc = 0.f;
#pragma unroll 8
        for (int d = 0; d < 128; d++) {
            float2 qf = __half22float2(qp[d]);
            float2 kf = __half22float2(kp[d]);
            acc = fmaf(qf.x, kf.x, acc);
            acc = fmaf(qf.y, kf.y, acc);
        }
        satt[tid] = acc * 0.0625f;
    }
    __syncthreads();

    if (tid < 20) {
        int base = tid * 10;
        float m = satt[base];
#pragma unroll
        for (int j = 1; j < 10; j++) m = fmaxf(m, satt[base + j]);
        float e[10]; float sum = 0.f;
#pragma unroll
        for (int j = 0; j < 10; j++) { e[j] = expf(satt[base + j] - m); sum += e[j]; }
        float inv = 1.0f / sum;
#pragma unroll
        for (int j = 0; j < 10; j++) satt[base + j] = e[j] * inv;
    }
    __syncthreads();

    __half* dst = o + (size_t)b * (N_ * D_);
    for (int idx = tid; idx < N_ * D_; idx += 256) {
        int d  = idx & 255;
        int hi = idx >> 8;
        int i  = hi % 10, h = hi / 10;
        const float* ap = satt + h * 100 + i * 10;
        const __half* vp = s16 + 1024 + h * 256 + d;
        float acc = 0.f;
#pragma unroll
        for (int j = 0; j < 10; j++) acc = fmaf(ap[j], __half2float(vp[j * QKVP]), acc);
        dst[i * 512 + h * 256 + d] = __float2half_rn(acc);
    }
}

// ---------------- layernorm (fp32 in -> fp16 out) ----------------
__global__ void ln_kernel(const float* __restrict__ y, const float* __restrict__ g,
                          const float* __restrict__ bt, __half* __restrict__ out16) {
    int row  = blockIdx.x * 8 + (threadIdx.x >> 5);
    int lane = threadIdx.x & 31;
    const float* p = y + (size_t)row * 512;
    float v[16];
#pragma unroll
    for (int q = 0; q < 4; q++) {
        float4 t = *(const float4*)(p + q * 128 + lane * 4);
        v[q*4+0] = t.x; v[q*4+1] = t.y; v[q*4+2] = t.z; v[q*4+3] = t.w;
    }
    float s = 0.f;
#pragma unroll
    for (int k = 0; k < 16; k++) s += v[k];
    s = warp_sum(s);
    float mu = s * (1.0f / 512.0f);
    float qs = 0.f;
#pragma unroll
    for (int k = 0; k < 16; k++) { float d = v[k] - mu; qs += d * d; }
    qs = warp_sum(qs);
    float inv = rsqrtf(qs * (1.0f / 512.0f) + 1e-5f);

#pragma unroll
    for (int q = 0; q < 4; q++) {
        int d0 = q * 128 + lane * 4;
        float r[4];
#pragma unroll
        for (int e = 0; e < 4; e++)
            r[e] = (v[q*4+e] - mu) * inv * g[d0+e] + bt[d0+e];
        __half2 hp0; hp0.x = __float2half_rn(r[0]); hp0.y = __float2half_rn(r[1]);
        __half2 hp1; hp1.x = __float2half_rn(r[2]); hp1.y = __float2half_rn(r[3]);
        *(__half2*)&out16[(size_t)row*512 + d0]   = hp0;
        *(__half2*)&out16[(size_t)row*512 + d0+2] = hp1;
    }
}

// ---------------- fused LN2 + LNf (fp32 in -> fp32 out) ----------------
__global__ void ln2f_kernel(const float* __restrict__ y,
                            const float* __restrict__ g2, const float* __restrict__ b2,
                            const float* __restrict__ gf, const float* __restrict__ bf_,
                            float* __restrict__ out) {
    int row  = blockIdx.x * 8 + (threadIdx.x >> 5);
    int lane = threadIdx.x & 31;
    const float* p = y + (size_t)row * 512;
    float v[16];
#pragma unroll
    for (int q = 0; q < 4; q++) {
        float4 t = *(const float4*)(p + q * 128 + lane * 4);
        v[q*4+0] = t.x; v[q*4+1] = t.y; v[q*4+2] = t.z; v[q*4+3] = t.w;
    }
    float s = 0.f;
#pragma unroll
    for (int k = 0; k < 16; k++) s += v[k];
    s = warp_sum(s);
    float mu = s * (1.0f / 512.0f);
    float qs = 0.f;
#pragma unroll
    for (int k = 0; k < 16; k++) { float d = v[k] - mu; qs += d * d; }
    qs = warp_sum(qs);
    float inv = rsqrtf(qs * (1.0f / 512.0f) + 1e-5f);
#pragma unroll
    for (int k = 0; k < 16; k++) {
        int d = (k >> 2) * 128 + lane * 4 + (k & 3);
        v[k] = (v[k] - mu) * inv * g2[d] + b2[d];
    }
    s = 0.f;
#pragma unroll
    for (int k = 0; k < 16; k++) s += v[k];
    s = warp_sum(s);
    float mu2 = s * (1.0f / 512.0f);
    qs = 0.f;
#pragma unroll
    for (int k = 0; k < 16; k++) { float d = v[k] - mu2; qs += d * d; }
    qs = warp_sum(qs);
    float inv2 = rsqrtf(qs * (1.0f / 512.0f) + 1e-5f);

    float* op = out + (size_t)row * 512;
#pragma unroll
    for (int q = 0; q < 4; q++) {
        int d0 = q * 128 + lane * 4;
        float4 r;
        r.x = (v[q*4+0] - mu2) * inv2 * gf[d0+0] + bf_[d0+0];
        r.y = (v[q*4+1] - mu2) * inv2 * gf[d0+1] + bf_[d0+1];
        r.z = (v[q*4+2] - mu2) * inv2 * gf[d0+2] + bf_[d0+2];
        r.w = (v[q*4+3] - mu2) * inv2 * gf[d0+3] + bf_[d0+3];
        *(float4*)(op + d0) = r;
    }
}

// ---------------- launcher ----------------
extern "C" void kernel_launch(void* const* d_in, const int* in_sizes, int n_in,
                              void* d_out, int out_size) {
    const float* boxes = (const float*)d_in[0];
    const float* w_in  = (const float*)d_in[1];
    const float* b_in  = (const float*)d_in[2];
    const float* wqkv  = (const float*)d_in[3];
    const float* bqkv  = (const float*)d_in[4];
    const float* wo    = (const float*)d_in[5];
    const float* bo    = (const float*)d_in[6];
    const float* ln1w  = (const float*)d_in[7];
    const float* ln1b  = (const float*)d_in[8];
    const float* w1    = (const float*)d_in[9];
    const float* b1    = (const float*)d_in[10];
    const float* w2    = (const float*)d_in[11];
    const float* b2    = (const float*)d_in[12];
    const float* ln2w  = (const float*)d_in[13];
    const float* ln2b  = (const float*)d_in[14];
    const float* lnfw  = (const float*)d_in[15];
    const float* lnfb  = (const float*)d_in[16];
    float* out = (float*)d_out;

    float *rel, *yb, *wc, *bc;
    __half *x16, *qkv16, *o16, *x116, *h16;
    __half *wo16, *w116, *w216;
    cudaGetSymbolAddress((void**)&rel,   g_rel);
    cudaGetSymbolAddress((void**)&yb,    g_y);
    cudaGetSymbolAddress((void**)&wc,    g_wc);
    cudaGetSymbolAddress((void**)&bc,    g_bc);
    cudaGetSymbolAddress((void**)&x16,   g_x16);
    cudaGetSymbolAddress((void**)&qkv16, g_qkv16);
    cudaGetSymbolAddress((void**)&o16,   g_o16);
    cudaGetSymbolAddress((void**)&x116,  g_x116);
    cudaGetSymbolAddress((void**)&h16,   g_h16);
    cudaGetSymbolAddress((void**)&wo16,  g_wo16);
    cudaGetSymbolAddress((void**)&w116,  g_w116);
    cudaGetSymbolAddress((void**)&w216,  g_w216);

    cudaFuncSetAttribute(mma_gemm<1,512>, cudaFuncAttributeMaxDynamicSharedMemorySize, SMEM_G);
    cudaFuncSetAttribute(mma_gemm<2,512>, cudaFuncAttributeMaxDynamicSharedMemorySize, SMEM_G);

    // 0) convert weights to fp16 + compose qkv weights (warp-per-output)
    cvtw_kernel<<<(D_*D_/4 + 255)/256, 256>>>(wo, wo16, D_*D_/4);
    cvtw_kernel<<<(D_*D_/4 + 255)/256, 256>>>(w1, w116, D_*D_/4);
    cvtw_kernel<<<(D_*D_/4 + 255)/256, 256>>>(w2, w216, D_*D_/4);
    wc_kernel<<<(1536*21 + 7)/8, 256>>>(wqkv, w_in, b_in, bqkv, wc, bc);
    // 1) relationships
    rel_kernel<<<B_/4, 128>>>(boxes, rel);
    // 2) fused projection: x16 + qkv16 directly from rel (composed weights)
    proj_kernel<<<dim3(T_/32, 4), 256>>>(rel, w_in, b_in, wc, bc, x16, qkv16);
    // 4) attention -> fp16
    int attn_smem = 10 * QKVP * (int)sizeof(__half);
    cudaFuncSetAttribute(attn_kernel, cudaFuncAttributeMaxDynamicSharedMemorySize, attn_smem);
    attn_kernel<<<B_, 256, attn_smem>>>(qkv16, o16);
    // 5) y1 = x16 + o @ wo^T + bo  -> fp32
    mma_gemm<1,512><<<dim3(4, T_/128), 512, SMEM_G>>>(o16, wo16, bo, x16, yb, nullptr);
    // 6) x1 = LN1(y1) -> fp16
    ln_kernel<<<T_/8, 256>>>(yb, ln1w, ln1b, x116);
    // 7) h = gelu(x1 @ w1^T + b1)  -> fp16
    mma_gemm<2,512><<<dim3(4, T_/128), 512, SMEM_G>>>(x116, w116, b1, nullptr, nullptr, h16);
    // 8) y2 = x116 + h @ w2^T + b2  -> fp32
    mma_gemm<1,512><<<dim3(4, T_/128), 512, SMEM_G>>>(h16, w216, b2, x116, yb, nullptr);
    // 9) out = LNf(LN2(y2))
    ln2f_kernel<<<T_/8, 256>>>(yb, ln2w, ln2b, lnfw, lnfb, out);
}